// round 8
// baseline (speedup 1.0000x reference)
#include <cuda_runtime.h>

// out[n, k=9*i+j, h, w] = sum_z A[n,z,h,w] * B[n,z, h+j-4, w+i-4]  (zero pad)
// N=8, Z=128, H=W=160.
//
// CTA tile TW=32 x TH=8. Threads (tx=4, h=8, j=9) = 288; warp == one j.
// Thread: 8 consecutive pixels, one row, 9 i-shifts -> 72 scalar accumulators.
// ZC=2 z-chunks, FOUR smem buffers, cp.async depth-3 pipeline, chunk loop
// unrolled x4 so all buffer offsets are compile-time immediates.

#define N_  8
#define Z_  128
#define H_  160
#define W_  160
#define TW  32
#define TH  8
#define ZC  2
#define NCH (Z_ / ZC)     // 64
#define AROW 36
#define BROW 44
#define BRN  16           // TH + 8
#define NT  288

#define ASZ (ZC * TH * AROW)      // 576 floats per A buffer
#define BSZ (ZC * BRN * BROW)     // 1408 floats per B buffer

__global__ __launch_bounds__(NT, 2)
void corr_kernel(const float* __restrict__ A,
                 const float* __restrict__ B,
                 float* __restrict__ out)
{
    __shared__ float As[4][ZC][TH][AROW];   // 4 * 2.25 KB
    __shared__ float Bs[4][ZC][BRN][BROW];  // 4 * 5.5 KB   (total 31 KB)

    const int tid = threadIdx.x;
    const int tx = tid & 3;          // w = w0 + 8*tx .. +7
    const int h  = (tid >> 2) & 7;
    const int j  = tid >> 5;         // warp index

    const int w0 = blockIdx.x * TW;
    const int h0 = blockIdx.y * TH;
    const int n  = blockIdx.z;

    const size_t plane = (size_t)H_ * W_;
    const float* Abase = A + (size_t)n * Z_ * plane;
    const float* Bbase = B + (size_t)n * Z_ * plane;

    // ------- fixed fill roles (computed once) -------
    // B: ZC*16*10 = 320 float4/chunk; slot 0: all threads, slot 1: tid<32.
    unsigned boff[2];
    unsigned bsm[2];
    int      bsz[2];
    bool     bact[2];
    #pragma unroll
    for (int s = 0; s < 2; s++) {
        int idx = tid + s * NT;
        bool act = idx < ZC * BRN * 10;
        int ii = act ? idx : 0;
        int z = ii / 160;
        int rem = ii - z * 160;
        int r = rem / 10;
        int c = rem - r * 10;
        int gh = h0 - 4 + r;
        int gw = w0 - 4 + 4 * c;
        bool v = ((unsigned)gh < H_) && ((unsigned)gw <= (W_ - 4));
        bact[s] = act;
        bsz[s] = v ? 16 : 0;
        boff[s] = v ? (unsigned)(z * plane + gh * W_ + gw) : 0u;
        bsm[s] = (unsigned)__cvta_generic_to_shared(&Bs[0][z][r][4 * c]);
    }
    // A: ZC*8*8 = 128 float4/chunk (tid < 128)
    const bool aact = tid < ZC * TH * 8;
    int ai = aact ? tid : 0;
    int az = ai >> 6;
    int ar = (ai >> 3) & 7;
    int ac = ai & 7;
    const unsigned aoff = (unsigned)(az * plane + (h0 + ar) * W_ + w0 + 4 * ac);
    const unsigned asm0 = (unsigned)__cvta_generic_to_shared(&As[0][az][ar][4 * ac]);

    // read-side base pointers (buffer 0)
    const float* aRd = &As[0][0][h][8 * tx];
    const float* bRd = &Bs[0][0][h + j][8 * tx];

    float acc[9][8];
    #pragma unroll
    for (int i = 0; i < 9; i++)
        #pragma unroll
        for (int p = 0; p < 8; p++)
            acc[i][p] = 0.0f;

    auto issue = [&](int chunk, int buf) {
        const float* bsrc = Bbase + (size_t)chunk * ZC * plane;
        const float* asrc = Abase + (size_t)chunk * ZC * plane;
        const unsigned bo = (unsigned)(buf * (BSZ * 4));
        const unsigned ao = (unsigned)(buf * (ASZ * 4));
        if (bact[0])
            asm volatile("cp.async.cg.shared.global [%0], [%1], 16, %2;"
                         :: "r"(bsm[0] + bo), "l"(bsrc + boff[0]), "r"(bsz[0]));
        if (bact[1])
            asm volatile("cp.async.cg.shared.global [%0], [%1], 16, %2;"
                         :: "r"(bsm[1] + bo), "l"(bsrc + boff[1]), "r"(bsz[1]));
        if (aact)
            asm volatile("cp.async.cg.shared.global [%0], [%1], 16, 16;"
                         :: "r"(asm0 + ao), "l"(asrc + aoff));
        asm volatile("cp.async.commit_group;");
    };

    // prologue: 3 chunks in flight
    issue(0, 0);
    issue(1, 1);
    issue(2, 2);

    for (int cg = 0; cg < NCH; cg += 4) {
        #pragma unroll
        for (int u = 0; u < 4; u++) {
            const int ch = cg + u;
            const int rem = NCH - 1 - ch;
            if (rem >= 2)      asm volatile("cp.async.wait_group 2;");
            else if (rem == 1) asm volatile("cp.async.wait_group 1;");
            else               asm volatile("cp.async.wait_group 0;");
            __syncthreads();   // chunk ch visible; buffer (u+3)&3 fully drained

            if (ch + 3 < NCH) issue(ch + 3, (u + 3) & 3);

            // compute chunk ch from buffer u (all offsets immediate)
            #pragma unroll
            for (int z = 0; z < ZC; z++) {
                const float* ap = aRd + u * ASZ + z * (TH * AROW);
                const float* bp = bRd + u * BSZ + z * (BRN * BROW);
                const float4 a0 = *(const float4*)(ap);
                const float4 a1 = *(const float4*)(ap + 4);
                const float4 b0 = *(const float4*)(bp);
                const float4 b1 = *(const float4*)(bp + 4);
                const float4 b2 = *(const float4*)(bp + 8);
                const float4 b3 = *(const float4*)(bp + 12);

                const float a[8] = {a0.x, a0.y, a0.z, a0.w,
                                    a1.x, a1.y, a1.z, a1.w};
                const float b[16] = {b0.x, b0.y, b0.z, b0.w,
                                     b1.x, b1.y, b1.z, b1.w,
                                     b2.x, b2.y, b2.z, b2.w,
                                     b3.x, b3.y, b3.z, b3.w};

                #pragma unroll
                for (int i = 0; i < 9; i++)
                    #pragma unroll
                    for (int p = 0; p < 8; p++)
                        acc[i][p] += a[p] * b[p + i];
            }
        }
    }

    // ------- store: 18 x STG.128 -------
    float* ob = out + (((size_t)n * 81 + j) * H_ + (h0 + h)) * W_ + w0 + 8 * tx;
    #pragma unroll
    for (int i = 0; i < 9; i++) {
        *(float4*)(ob + (size_t)(9 * i) * plane) =
            make_float4(acc[i][0], acc[i][1], acc[i][2], acc[i][3]);
        *(float4*)(ob + (size_t)(9 * i) * plane + 4) =
            make_float4(acc[i][4], acc[i][5], acc[i][6], acc[i][7]);
    }
}

extern "C" void kernel_launch(void* const* d_in, const int* in_sizes, int n_in,
                              void* d_out, int out_size)
{
    const float* imgA = (const float*)d_in[0];
    const float* imgB = (const float*)d_in[1];
    float* out = (float*)d_out;

    dim3 grid(W_ / TW, H_ / TH, N_);
    corr_kernel<<<grid, NT>>>(imgA, imgB, out);
}

// round 9
// speedup vs baseline: 1.4536x; 1.4536x over previous
#include <cuda_runtime.h>

// out[n, k=9*i+j, h, w] = sum_z A[n,z,h,w] * B[n,z, h+j-4, w+i-4]  (zero pad)
// N=8, Z=128, H=W=160.
//
// CTA tile TW=32 x TH=8, NT=256 (8 warps -> perfect SMSP balance 2/2/2/2).
// Warp w: primary j=w, thread = 8 consecutive px, one row, 9 i -> 72 acc.
//         secondary j=8 for row h0+w, one px per lane (l -> w0+l), 9 i -> 9 acc.
// ZC=4 z-chunks, triple-buffered smem via cp.async.cg (zfill halo), one barrier.

#define N_  8
#define Z_  128
#define H_  160
#define W_  160
#define TW  32
#define TH  8
#define ZC  4
#define NCH (Z_ / ZC)     // 32
#define AROW 36
#define BROW 44
#define BRN  16           // TH + 8
#define NT  256

#define ASZ (ZC * TH * AROW)      // floats per A buffer
#define BSZ (ZC * BRN * BROW)     // floats per B buffer

__global__ __launch_bounds__(NT, 2)
void corr_kernel(const float* __restrict__ A,
                 const float* __restrict__ B,
                 float* __restrict__ out)
{
    __shared__ float As[3][ZC][TH][AROW];   // 3 * 4.5 KB
    __shared__ float Bs[3][ZC][BRN][BROW];  // 3 * 11 KB  (46.5 KB)

    const int tid = threadIdx.x;
    const int tx  = tid & 3;          // w = w0 + 8*tx .. +7
    const int h   = (tid >> 2) & 7;
    const int wid = tid >> 5;         // warp id == primary j (0..7)
    const int l   = tid & 31;         // lane

    const int w0 = blockIdx.x * TW;
    const int h0 = blockIdx.y * TH;
    const int n  = blockIdx.z;

    const size_t plane = (size_t)H_ * W_;
    const float* Abase = A + (size_t)n * Z_ * plane;
    const float* Bbase = B + (size_t)n * Z_ * plane;

    // ------- fixed fill roles -------
    // B: ZC*16*10 = 640 float4/chunk, slots idx = tid + 256*s, s=0..2
    unsigned boff[3];
    unsigned bsm[3];
    int      bsz[3];
    bool     bact[3];
    #pragma unroll
    for (int s = 0; s < 3; s++) {
        int idx = tid + s * NT;
        bool act = idx < ZC * BRN * 10;
        int ii = act ? idx : 0;
        int z = ii / 160;
        int rem = ii - z * 160;
        int r = rem / 10;
        int c = rem - r * 10;
        int gh = h0 - 4 + r;
        int gw = w0 - 4 + 4 * c;
        bool v = ((unsigned)gh < H_) && ((unsigned)gw <= (W_ - 4));
        bact[s] = act;
        bsz[s] = v ? 16 : 0;
        boff[s] = v ? (unsigned)(z * plane + gh * W_ + gw) : 0u;
        bsm[s] = (unsigned)__cvta_generic_to_shared(&Bs[0][z][r][4 * c]);
    }
    // A: ZC*8*8 = 256 float4/chunk -> exactly one per thread
    const int az = tid >> 6;
    const int ar = (tid >> 3) & 7;
    const int ac = tid & 7;
    const unsigned aoff = (unsigned)(az * plane + (h0 + ar) * W_ + w0 + 4 * ac);
    const unsigned asm0 = (unsigned)__cvta_generic_to_shared(&As[0][az][ar][4 * ac]);

    // read-side base pointers (buffer 0)
    const float* aRd  = &As[0][0][h][8 * tx];          // primary A
    const float* bRd  = &Bs[0][0][h + wid][8 * tx];    // primary B row h+j
    const float* aRd2 = &As[0][0][wid][l];             // secondary A (row wid, px l)
    const float* bRd2 = &Bs[0][0][wid + 8][l];         // secondary B row (j=8)

    float acc[9][8];
    #pragma unroll
    for (int i = 0; i < 9; i++)
        #pragma unroll
        for (int p = 0; p < 8; p++)
            acc[i][p] = 0.0f;
    float acc_s[9];
    #pragma unroll
    for (int i = 0; i < 9; i++) acc_s[i] = 0.0f;

    auto issue = [&](int chunk, int buf) {
        const float* bsrc = Bbase + (size_t)chunk * ZC * plane;
        const float* asrc = Abase + (size_t)chunk * ZC * plane;
        const unsigned bo = (unsigned)(buf * (BSZ * 4));
        const unsigned ao = (unsigned)(buf * (ASZ * 4));
        #pragma unroll
        for (int s = 0; s < 3; s++) {
            if (bact[s]) {
                asm volatile("cp.async.cg.shared.global [%0], [%1], 16, %2;"
                             :: "r"(bsm[s] + bo), "l"(bsrc + boff[s]), "r"(bsz[s]));
            }
        }
        asm volatile("cp.async.cg.shared.global [%0], [%1], 16, 16;"
                     :: "r"(asm0 + ao), "l"(asrc + aoff));
        asm volatile("cp.async.commit_group;");
    };

    // prologue: 2 chunks in flight
    issue(0, 0);
    issue(1, 1);

    int bufc = 0;
    for (int ch = 0; ch < NCH; ch++) {
        if (ch < NCH - 1) asm volatile("cp.async.wait_group 1;");
        else              asm volatile("cp.async.wait_group 0;");
        __syncthreads();

        int nb = bufc + 2; if (nb >= 3) nb -= 3;
        if (ch + 2 < NCH) issue(ch + 2, nb);

        const float* ap0 = aRd  + bufc * ASZ;
        const float* bp0 = bRd  + bufc * BSZ;
        const float* ap2 = aRd2 + bufc * ASZ;
        const float* bp2 = bRd2 + bufc * BSZ;

        #pragma unroll
        for (int z = 0; z < ZC; z++) {
            const float4 a0 = *(const float4*)(ap0 + z * (TH * AROW));
            const float4 a1 = *(const float4*)(ap0 + z * (TH * AROW) + 4);
            const float4 b0 = *(const float4*)(bp0 + z * (BRN * BROW));
            const float4 b1 = *(const float4*)(bp0 + z * (BRN * BROW) + 4);
            const float4 b2 = *(const float4*)(bp0 + z * (BRN * BROW) + 8);
            const float4 b3 = *(const float4*)(bp0 + z * (BRN * BROW) + 12);

            const float a[8] = {a0.x, a0.y, a0.z, a0.w, a1.x, a1.y, a1.z, a1.w};
            const float b[16] = {b0.x, b0.y, b0.z, b0.w, b1.x, b1.y, b1.z, b1.w,
                                 b2.x, b2.y, b2.z, b2.w, b3.x, b3.y, b3.z, b3.w};

            #pragma unroll
            for (int i = 0; i < 9; i++)
                #pragma unroll
                for (int p = 0; p < 8; p++)
                    acc[i][p] += a[p] * b[p + i];

            // secondary: j=8, row h0+wid, pixel w0+l
            const float a2 = ap2[z * (TH * AROW)];
            #pragma unroll
            for (int i = 0; i < 9; i++)
                acc_s[i] += a2 * bp2[z * (BRN * BROW) + i];
        }

        bufc = (bufc == 2) ? 0 : bufc + 1;
    }

    // ------- primary store: 18 x STG.128 (k = 9*i + wid) -------
    float* ob = out + (((size_t)n * 81 + wid) * H_ + (h0 + h)) * W_ + w0 + 8 * tx;
    #pragma unroll
    for (int i = 0; i < 9; i++) {
        *(float4*)(ob + (size_t)(9 * i) * plane) =
            make_float4(acc[i][0], acc[i][1], acc[i][2], acc[i][3]);
        *(float4*)(ob + (size_t)(9 * i) * plane + 4) =
            make_float4(acc[i][4], acc[i][5], acc[i][6], acc[i][7]);
    }
    // ------- secondary store: 9 x STG.32 (k = 9*i + 8, row h0+wid, px w0+l) -------
    float* ob2 = out + (((size_t)n * 81 + 8) * H_ + (h0 + wid)) * W_ + w0 + l;
    #pragma unroll
    for (int i = 0; i < 9; i++)
        ob2[(size_t)(9 * i) * plane] = acc_s[i];
}

extern "C" void kernel_launch(void* const* d_in, const int* in_sizes, int n_in,
                              void* d_out, int out_size)
{
    const float* imgA = (const float*)d_in[0];
    const float* imgB = (const float*)d_in[1];
    float* out = (float*)d_out;

    dim3 grid(W_ / TW, H_ / TH, N_);
    corr_kernel<<<grid, NT>>>(imgA, imgB, out);
}